// round 9
// baseline (speedup 1.0000x reference)
#include <cuda_runtime.h>
#include <cuda_bf16.h>
#include <math.h>
#include <stdint.h>

// Problem constants
#define DDIM 1024
#define TDIM 2048
#define BDIM 32
#define MTOT 65536
#define WSTRIDE 2048        // W row stride in floats (2*D)

// GEMM tiling (bf16)
#define BM 128
#define BN 256
#define BK 64               // bf16 k-elements per stage
#define NTILES 4            // 1024 / BN
#define KT 16               // 1024 / BK
#define STAGES 3

#define STAGEB_A 18432u     // 128 rows * 144B
#define STAGEB_B 36864u     // 256 rows * 144B
#define SMEM_PART 165888u   // 3*(A+B)
#define SMEM_TOTAL 169984u  // + partial[8][128] floats

// Scratch (static __device__ arrays: allocation-free)
__device__ __nv_bfloat16 g_encb[(size_t)MTOT * DDIM];
__device__ __nv_bfloat16 g_w2b[(size_t)DDIM * DDIM];
__device__ float g_qh[BDIM * DDIM];
__device__ float g_part[(size_t)NTILES * MTOT];

// ---------------------------------------------------------------------------
__device__ __forceinline__ void mma_bf16(float* d, const uint32_t* a, uint32_t b0, uint32_t b1) {
    asm volatile(
        "mma.sync.aligned.m16n8k16.row.col.f32.bf16.bf16.f32 "
        "{%0,%1,%2,%3}, {%4,%5,%6,%7}, {%8,%9}, {%0,%1,%2,%3};"
        : "+f"(d[0]), "+f"(d[1]), "+f"(d[2]), "+f"(d[3])
        : "r"(a[0]), "r"(a[1]), "r"(a[2]), "r"(a[3]), "r"(b0), "r"(b1));
}
__device__ __forceinline__ void cp16(uint32_t dst, const void* src) {
    asm volatile("cp.async.cg.shared.global [%0], [%1], 16;" :: "r"(dst), "l"(src));
}
#define LDSM4(r0, r1, r2, r3, addr) \
    asm volatile("ldmatrix.sync.aligned.m8n8.x4.shared.b16 {%0,%1,%2,%3}, [%4];" \
        : "=r"(r0), "=r"(r1), "=r"(r2), "=r"(r3) : "r"(addr))

__device__ __forceinline__ uint32_t smem_u32(const void* p) {
    uint32_t a;
    asm("{ .reg .u64 t; cvta.to.shared.u64 t, %1; cvt.u32.u64 %0, t; }" : "=r"(a) : "l"(p));
    return a;
}

// ---------------------------------------------------------------------------
// Convert enc (f32) -> g_encb (bf16). One float4 per thread.
__global__ __launch_bounds__(256) void conv_enc(const float4* __restrict__ src)
{
    const size_t i = (size_t)blockIdx.x * 256 + threadIdx.x;
    const float4 x = src[i];
    __nv_bfloat162 p0 = __floats2bfloat162_rn(x.x, x.y);
    __nv_bfloat162 p1 = __floats2bfloat162_rn(x.z, x.w);
    uint2 o;
    o.x = *(uint32_t*)&p0;
    o.y = *(uint32_t*)&p1;
    ((uint2*)g_encb)[i] = o;
}

// Convert W2 = W[:, 1024:2048] -> g_w2b (bf16).
__global__ __launch_bounds__(256) void conv_w2(const float* __restrict__ W)
{
    const int n = blockIdx.x;
    const int t = threadIdx.x;
    const float4 x = *(const float4*)(W + (size_t)n * WSTRIDE + DDIM + t * 4);
    __nv_bfloat162 p0 = __floats2bfloat162_rn(x.x, x.y);
    __nv_bfloat162 p1 = __floats2bfloat162_rn(x.z, x.w);
    uint2 o;
    o.x = *(uint32_t*)&p0;
    o.y = *(uint32_t*)&p1;
    ((uint2*)(g_w2b + (size_t)n * DDIM))[t] = o;
}

// ---------------------------------------------------------------------------
// qh[b,d] = W1[d,:] . hidden[b,:] + bias[d]
__global__ __launch_bounds__(256) void qh_kernel(
    const float* __restrict__ hidden, const float* __restrict__ W,
    const float* __restrict__ bias)
{
    const int b = blockIdx.y;
    const int warp = threadIdx.x >> 5;
    const int lane = threadIdx.x & 31;
    const int d = blockIdx.x * 8 + warp;

    const float* wr = W + (size_t)d * WSTRIDE;
    const float* h  = hidden + (size_t)b * DDIM;

    float acc = 0.f;
    #pragma unroll 8
    for (int k = lane; k < DDIM; k += 32) acc += wr[k] * h[k];
    #pragma unroll
    for (int o = 16; o > 0; o >>= 1) acc += __shfl_xor_sync(0xFFFFFFFFu, acc, o);
    if (lane == 0) g_qh[(size_t)b * DDIM + d] = acc + bias[d];
}

// ---------------------------------------------------------------------------
// bf16 GEMM: 128x256 tile, 512 threads (16 warps, 64x32 warp tiles),
// 3-stage cp.async pipeline, single-buffered ldmatrix fragments (TLP hiding).
__global__ __launch_bounds__(512, 1) void bf_gemm(const float* __restrict__ v)
{
    extern __shared__ char smem[];
    const uint32_t uAs = smem_u32(smem);              // A stages
    const uint32_t uBs = uAs + STAGES * STAGEB_A;     // B stages

    const int tid  = threadIdx.x;
    const int lane = tid & 31;
    const int warp = tid >> 5;
    const int wm   = warp >> 3;     // 0..1 (M, 64 rows)
    const int wn   = warp & 7;      // 0..7 (N, 32 cols)
    const int gid  = lane >> 2;
    const int tig  = lane & 3;

    const int nx   = blockIdx.x;
    const int m0   = blockIdx.y * BM;
    const int n0   = nx * BN;
    const int bidx = m0 >> 11;

    float acc[4][4][4];
    #pragma unroll
    for (int i = 0; i < 4; i++)
        #pragma unroll
        for (int j = 0; j < 4; j++)
            #pragma unroll
            for (int k = 0; k < 4; k++) acc[i][j][k] = 0.f;

    // cp.async mapping: 512 threads; A = 128 rows x 8 chunks (2/thr), B = 256 rows x 8 (4/thr)
    const int r0 = tid >> 3;            // 0..63
    const int c8 = tid & 7;             // 0..7
    const uint32_t dA = uAs + (uint32_t)r0 * 144 + (uint32_t)c8 * 16;
    const uint32_t dB = uBs + (uint32_t)r0 * 144 + (uint32_t)c8 * 16;
    const __nv_bfloat16* pA = g_encb + (size_t)(m0 + r0) * DDIM + c8 * 8;
    const __nv_bfloat16* pB = g_w2b  + (size_t)(n0 + r0) * DDIM + c8 * 8;

    #define ISSUE_TILE(c, s)                                                      \
    do {                                                                          \
        const uint32_t _sa = (uint32_t)(s) * STAGEB_A;                            \
        const uint32_t _sb = (uint32_t)(s) * STAGEB_B;                            \
        const __nv_bfloat16* _ga = pA + (size_t)(c) * BK;                         \
        const __nv_bfloat16* _gb = pB + (size_t)(c) * BK;                         \
        cp16(dA + _sa,         _ga);                                              \
        cp16(dA + _sa + 9216u, _ga + (size_t)64 * DDIM);                          \
        _Pragma("unroll")                                                         \
        for (int j = 0; j < 4; j++)                                               \
            cp16(dB + _sb + (uint32_t)j * 9216u, _gb + (size_t)j * 64 * DDIM);    \
        asm volatile("cp.async.commit_group;");                                   \
    } while (0)

    // ldmatrix base addresses (lane-dependent)
    const uint32_t aBase = uAs + (uint32_t)(wm * 64 + (lane & 15)) * 144 + (uint32_t)(lane >> 4) * 16;
    const uint32_t bBase = uBs + (uint32_t)(wn * 32 + (lane & 15)) * 144 + (uint32_t)(lane >> 4) * 16;

    uint32_t fa[4][4];
    uint32_t fb[2][4];

    // B fragments issued first: they are consumed by the first mma alongside fa,
    // and issuing them ahead of the 4 A-LDSMs buys extra latency cover.
    #define LOADF(sA, sB, ks)                                                    \
    do {                                                                         \
        const uint32_t _oa = (uint32_t)(sA) * STAGEB_A + (uint32_t)(ks) * 32u;   \
        const uint32_t _ob = (uint32_t)(sB) * STAGEB_B + (uint32_t)(ks) * 32u;   \
        _Pragma("unroll")                                                        \
        for (int q = 0; q < 2; q++)                                              \
            LDSM4(fb[q][0], fb[q][1], fb[q][2], fb[q][3],                        \
                  bBase + _ob + (uint32_t)q * 2304u);                            \
        _Pragma("unroll")                                                        \
        for (int mi = 0; mi < 4; mi++)                                           \
            LDSM4(fa[mi][0], fa[mi][1], fa[mi][2], fa[mi][3],                    \
                  aBase + _oa + (uint32_t)mi * 2304u);                           \
    } while (0)

    #define COMP()                                                               \
    do {                                                                         \
        _Pragma("unroll")                                                        \
        for (int mi = 0; mi < 4; mi++)                                           \
            _Pragma("unroll")                                                    \
            for (int ni = 0; ni < 4; ni++)                                       \
                mma_bf16(acc[mi][ni], fa[mi],                                    \
                         fb[ni >> 1][ni & 1], fb[ni >> 1][2 + (ni & 1)]);        \
    } while (0)

    // Prologue: fill stages 0 and 1; stage 0 resident before first frag load.
    ISSUE_TILE(0, 0);
    ISSUE_TILE(1, 1);
    asm volatile("cp.async.wait_group 1;");
    __syncthreads();

    for (int kt = 0; kt < KT; kt++) {
        const int s = kt % STAGES;
        LOADF(s, s, 0);
        if (kt + 2 < KT) ISSUE_TILE(kt + 2, (kt + 2) % STAGES);  // slot (kt-1): drained
        COMP();
        LOADF(s, s, 1); COMP();
        LOADF(s, s, 2); COMP();
        LOADF(s, s, 3); COMP();
        if (kt + 1 < KT) {
            if (kt + 2 < KT) asm volatile("cp.async.wait_group 1;");
            else             asm volatile("cp.async.wait_group 0;");
            __syncthreads();
        }
    }

    // Epilogue: relu(acc + qh) * v, reduced over this CTA's 256 d-columns.
    float* partial = (float*)(smem + SMEM_PART);   // [8][128]
    float pr[4][2];
    #pragma unroll
    for (int mi = 0; mi < 4; mi++) { pr[mi][0] = 0.f; pr[mi][1] = 0.f; }

    #pragma unroll
    for (int ni = 0; ni < 4; ni++) {
        const int c = n0 + wn * 32 + ni * 8 + tig * 2;
        const float q0 = g_qh[(size_t)bidx * DDIM + c];
        const float q1 = g_qh[(size_t)bidx * DDIM + c + 1];
        const float v0 = v[c];
        const float v1 = v[c + 1];
        #pragma unroll
        for (int mi = 0; mi < 4; mi++) {
            pr[mi][0] += fmaxf(acc[mi][ni][0] + q0, 0.f) * v0;
            pr[mi][0] += fmaxf(acc[mi][ni][1] + q1, 0.f) * v1;
            pr[mi][1] += fmaxf(acc[mi][ni][2] + q0, 0.f) * v0;
            pr[mi][1] += fmaxf(acc[mi][ni][3] + q1, 0.f) * v1;
        }
    }

    __syncthreads();
    #pragma unroll
    for (int mi = 0; mi < 4; mi++)
        #pragma unroll
        for (int j = 0; j < 2; j++) {
            float p = pr[mi][j];
            p += __shfl_xor_sync(0xFFFFFFFFu, p, 1);
            p += __shfl_xor_sync(0xFFFFFFFFu, p, 2);
            if (tig == 0) partial[wn * BM + wm * 64 + mi * 16 + j * 8 + gid] = p;
        }
    __syncthreads();

    if (tid < BM) {
        float s = 0.f;
        #pragma unroll
        for (int q = 0; q < 8; q++) s += partial[q * BM + tid];
        g_part[(size_t)nx * MTOT + m0 + tid] = s;
    }
}

// ---------------------------------------------------------------------------
// Sum 4 N-strip partials -> scores, softmax over T.
__global__ __launch_bounds__(256) void softmax_kernel(float* __restrict__ out)
{
    const int b = blockIdx.x;
    const int tid = threadIdx.x;
    __shared__ float red[256];

    float vals[8];
    float mx = -1e30f;
    #pragma unroll
    for (int j = 0; j < 8; j++) {
        const int t = tid + j * 256;
        float s = 0.f;
        #pragma unroll
        for (int nxi = 0; nxi < NTILES; nxi++)
            s += g_part[(size_t)nxi * MTOT + (size_t)b * TDIM + t];
        vals[j] = s;
        mx = fmaxf(mx, s);
    }

    red[tid] = mx;
    __syncthreads();
    #pragma unroll
    for (int o = 128; o > 0; o >>= 1) {
        if (tid < o) red[tid] = fmaxf(red[tid], red[tid + o]);
        __syncthreads();
    }
    const float m = red[0];
    __syncthreads();

    float sum = 0.f;
    #pragma unroll
    for (int j = 0; j < 8; j++) {
        vals[j] = expf(vals[j] - m);
        sum += vals[j];
    }
    red[tid] = sum;
    __syncthreads();
    #pragma unroll
    for (int o = 128; o > 0; o >>= 1) {
        if (tid < o) red[tid] += red[tid + o];
        __syncthreads();
    }
    const float inv = 1.f / red[0];

    #pragma unroll
    for (int j = 0; j < 8; j++)
        out[(size_t)b * TDIM + tid + j * 256] = vals[j] * inv;
}

// ---------------------------------------------------------------------------
extern "C" void kernel_launch(void* const* d_in, const int* in_sizes, int n_in,
                              void* d_out, int out_size)
{
    const float* hidden = (const float*)d_in[0];
    const float* enc    = (const float*)d_in[1];
    const float* W      = (const float*)d_in[2];
    const float* bias   = (const float*)d_in[3];
    const float* v      = (const float*)d_in[4];
    float* out = (float*)d_out;

    cudaFuncSetAttribute(bf_gemm, cudaFuncAttributeMaxDynamicSharedMemorySize, SMEM_TOTAL);

    conv_enc<<<65536, 256>>>((const float4*)enc);
    conv_w2<<<DDIM, 256>>>(W);
    qh_kernel<<<dim3(DDIM / 8, BDIM), 256>>>(hidden, W, bias);
    bf_gemm<<<dim3(NTILES, MTOT / BM), 512, SMEM_TOTAL>>>(v);
    softmax_kernel<<<BDIM, 256>>>(out);
}

// round 10
// speedup vs baseline: 1.0446x; 1.0446x over previous
#include <cuda_runtime.h>
#include <cuda_bf16.h>
#include <math.h>
#include <stdint.h>

// Problem constants
#define DDIM 1024
#define TDIM 2048
#define BDIM 32
#define MTOT 65536
#define WSTRIDE 2048        // W row stride in floats (2*D)

// GEMM tiling (bf16)
#define BM 128
#define BN 128
#define BK 64               // bf16 k-elements per stage
#define NTILES 8            // 1024 / BN
#define KT 16               // 1024 / BK
#define STAGES 3

#define STAGEB 18432u       // bytes per stage per matrix: 128 rows * 144B
#define SMEM_PART 110592u   // partial[] offset (after 3*(A+B) stages)
#define SMEM_TOTAL 112640u

// Scratch (static __device__ arrays: allocation-free)
__device__ __nv_bfloat16 g_encb[(size_t)MTOT * DDIM];
__device__ __nv_bfloat16 g_w2b[(size_t)DDIM * DDIM];
__device__ float g_qh[BDIM * DDIM];
__device__ float g_part[(size_t)NTILES * MTOT];

// ---------------------------------------------------------------------------
__device__ __forceinline__ void mma_bf16(float* d, const uint32_t* a, uint32_t b0, uint32_t b1) {
    asm volatile(
        "mma.sync.aligned.m16n8k16.row.col.f32.bf16.bf16.f32 "
        "{%0,%1,%2,%3}, {%4,%5,%6,%7}, {%8,%9}, {%0,%1,%2,%3};"
        : "+f"(d[0]), "+f"(d[1]), "+f"(d[2]), "+f"(d[3])
        : "r"(a[0]), "r"(a[1]), "r"(a[2]), "r"(a[3]), "r"(b0), "r"(b1));
}
__device__ __forceinline__ void cp16(uint32_t dst, const void* src) {
    asm volatile("cp.async.cg.shared.global [%0], [%1], 16;" :: "r"(dst), "l"(src));
}
#define LDSM4(r0, r1, r2, r3, addr) \
    asm volatile("ldmatrix.sync.aligned.m8n8.x4.shared.b16 {%0,%1,%2,%3}, [%4];" \
        : "=r"(r0), "=r"(r1), "=r"(r2), "=r"(r3) : "r"(addr))

__device__ __forceinline__ uint32_t smem_u32(const void* p) {
    uint32_t a;
    asm("{ .reg .u64 t; cvta.to.shared.u64 t, %1; cvt.u32.u64 %0, t; }" : "=r"(a) : "l"(p));
    return a;
}

// ---------------------------------------------------------------------------
// Convert enc (f32) -> g_encb (bf16). One float4 per thread.
__global__ __launch_bounds__(256) void conv_enc(const float4* __restrict__ src)
{
    const size_t i = (size_t)blockIdx.x * 256 + threadIdx.x;
    const float4 x = src[i];
    __nv_bfloat162 p0 = __floats2bfloat162_rn(x.x, x.y);
    __nv_bfloat162 p1 = __floats2bfloat162_rn(x.z, x.w);
    uint2 o;
    o.x = *(uint32_t*)&p0;
    o.y = *(uint32_t*)&p1;
    ((uint2*)g_encb)[i] = o;
}

// Convert W2 = W[:, 1024:2048] -> g_w2b (bf16).
__global__ __launch_bounds__(256) void conv_w2(const float* __restrict__ W)
{
    const int n = blockIdx.x;
    const int t = threadIdx.x;
    const float4 x = *(const float4*)(W + (size_t)n * WSTRIDE + DDIM + t * 4);
    __nv_bfloat162 p0 = __floats2bfloat162_rn(x.x, x.y);
    __nv_bfloat162 p1 = __floats2bfloat162_rn(x.z, x.w);
    uint2 o;
    o.x = *(uint32_t*)&p0;
    o.y = *(uint32_t*)&p1;
    ((uint2*)(g_w2b + (size_t)n * DDIM))[t] = o;
}

// ---------------------------------------------------------------------------
// qh[b,d] = W1[d,:] . hidden[b,:] + bias[d]
__global__ __launch_bounds__(256) void qh_kernel(
    const float* __restrict__ hidden, const float* __restrict__ W,
    const float* __restrict__ bias)
{
    const int b = blockIdx.y;
    const int warp = threadIdx.x >> 5;
    const int lane = threadIdx.x & 31;
    const int d = blockIdx.x * 8 + warp;

    const float* wr = W + (size_t)d * WSTRIDE;
    const float* h  = hidden + (size_t)b * DDIM;

    float acc = 0.f;
    #pragma unroll 8
    for (int k = lane; k < DDIM; k += 32) acc += wr[k] * h[k];
    #pragma unroll
    for (int o = 16; o > 0; o >>= 1) acc += __shfl_xor_sync(0xFFFFFFFFu, acc, o);
    if (lane == 0) g_qh[(size_t)b * DDIM + d] = acc + bias[d];
}

// ---------------------------------------------------------------------------
// bf16 GEMM: 128x128 tile, 512 threads (16 warps, 32x32 warp tiles),
// 3-stage cp.async pipeline, fragment ping-pong. ~95 regs: TLP + ILP, no spill.
__global__ __launch_bounds__(512, 1) void bf_gemm(const float* __restrict__ v)
{
    extern __shared__ char smem[];
    const uint32_t uAs = smem_u32(smem);              // A stages
    const uint32_t uBs = uAs + STAGES * STAGEB;       // B stages

    const int tid  = threadIdx.x;
    const int lane = tid & 31;
    const int warp = tid >> 5;
    const int wm   = warp >> 2;     // 0..3 (M, 32 rows)
    const int wn   = warp & 3;      // 0..3 (N, 32 cols)
    const int gid  = lane >> 2;
    const int tig  = lane & 3;

    const int nx   = blockIdx.x;
    const int m0   = blockIdx.y * BM;
    const int n0   = nx * BN;
    const int bidx = m0 >> 11;

    float acc[2][4][4];
    #pragma unroll
    for (int i = 0; i < 2; i++)
        #pragma unroll
        for (int j = 0; j < 4; j++)
            #pragma unroll
            for (int k = 0; k < 4; k++) acc[i][j][k] = 0.f;

    // cp.async mapping: 512 threads; A/B each 128 rows x 8 16B-chunks = 1024 ops (2/thr)
    const int r0 = tid >> 3;            // 0..63
    const int c8 = tid & 7;             // 0..7
    const uint32_t dA = uAs + (uint32_t)r0 * 144 + (uint32_t)c8 * 16;
    const uint32_t dB = uBs + (uint32_t)r0 * 144 + (uint32_t)c8 * 16;
    const __nv_bfloat16* pA = g_encb + (size_t)(m0 + r0) * DDIM + c8 * 8;
    const __nv_bfloat16* pB = g_w2b  + (size_t)(n0 + r0) * DDIM + c8 * 8;

    #define ISSUE_TILE(c, s)                                                     \
    do {                                                                         \
        const uint32_t _so = (uint32_t)(s) * STAGEB;                             \
        const __nv_bfloat16* _ga = pA + (size_t)(c) * BK;                        \
        const __nv_bfloat16* _gb = pB + (size_t)(c) * BK;                        \
        cp16(dA + _so,         _ga);                                             \
        cp16(dA + _so + 9216u, _ga + (size_t)64 * DDIM);                         \
        cp16(dB + _so,         _gb);                                             \
        cp16(dB + _so + 9216u, _gb + (size_t)64 * DDIM);                         \
        asm volatile("cp.async.commit_group;");                                  \
    } while (0)

    // ldmatrix base addresses (lane-dependent)
    const uint32_t aBase = uAs + (uint32_t)(wm * 32 + (lane & 15)) * 144 + (uint32_t)(lane >> 4) * 16;
    const uint32_t bBase = uBs + (uint32_t)(wn * 32 + (lane & 15)) * 144 + (uint32_t)(lane >> 4) * 16;

    uint32_t fa[2][2][4];
    uint32_t fb[2][2][4];

    // B issued first (extra latency cover before the first mma of COMP).
    #define LOADF(s, ks, p)                                                      \
    do {                                                                         \
        const uint32_t _o = (uint32_t)(s) * STAGEB + (uint32_t)(ks) * 32u;       \
        _Pragma("unroll")                                                        \
        for (int q = 0; q < 2; q++)                                              \
            LDSM4(fb[p][q][0], fb[p][q][1], fb[p][q][2], fb[p][q][3],            \
                  bBase + _o + (uint32_t)q * 2304u);                             \
        _Pragma("unroll")                                                        \
        for (int mi = 0; mi < 2; mi++)                                           \
            LDSM4(fa[p][mi][0], fa[p][mi][1], fa[p][mi][2], fa[p][mi][3],        \
                  aBase + _o + (uint32_t)mi * 2304u);                            \
    } while (0)

    // fb x4 pair q covers ni=2q (regs 0,2) and ni=2q+1 (regs 1,3)
    #define COMP(p)                                                              \
    do {                                                                         \
        _Pragma("unroll")                                                        \
        for (int mi = 0; mi < 2; mi++)                                           \
            _Pragma("unroll")                                                    \
            for (int ni = 0; ni < 4; ni++)                                       \
                mma_bf16(acc[mi][ni], fa[p][mi],                                 \
                         fb[p][ni >> 1][ni & 1], fb[p][ni >> 1][2 + (ni & 1)]);  \
    } while (0)

    // Prologue: fill stages 0 and 1; stage 0 resident before first frag load.
    ISSUE_TILE(0, 0);
    ISSUE_TILE(1, 1);
    asm volatile("cp.async.wait_group 1;");
    __syncthreads();
    LOADF(0, 0, 0);

    for (int kt = 0; kt < KT; kt++) {
        const int s = kt % STAGES;
        LOADF(s, 1, 1); COMP(0);                       // ks0
        if (kt + 2 < KT) ISSUE_TILE(kt + 2, (kt + 2) % STAGES);
        LOADF(s, 2, 0); COMP(1);                       // ks1
        LOADF(s, 3, 1); COMP(0);                       // ks2
        if (kt + 1 < KT) {
            if (kt + 2 < KT) asm volatile("cp.async.wait_group 1;");
            else             asm volatile("cp.async.wait_group 0;");
            __syncthreads();
            LOADF((kt + 1) % STAGES, 0, 0);            // next ks0, shadowed by COMP below
        }
        COMP(1);                                       // ks3
    }

    // Epilogue: relu(acc + qh) * v, reduced over this CTA's 128 d-columns.
    float* partial = (float*)(smem + SMEM_PART);   // [4][128]
    float pr[2][2];
    #pragma unroll
    for (int mi = 0; mi < 2; mi++) { pr[mi][0] = 0.f; pr[mi][1] = 0.f; }

    #pragma unroll
    for (int ni = 0; ni < 4; ni++) {
        const int c = n0 + wn * 32 + ni * 8 + tig * 2;
        const float q0 = g_qh[(size_t)bidx * DDIM + c];
        const float q1 = g_qh[(size_t)bidx * DDIM + c + 1];
        const float v0 = v[c];
        const float v1 = v[c + 1];
        #pragma unroll
        for (int mi = 0; mi < 2; mi++) {
            pr[mi][0] += fmaxf(acc[mi][ni][0] + q0, 0.f) * v0;
            pr[mi][0] += fmaxf(acc[mi][ni][1] + q1, 0.f) * v1;
            pr[mi][1] += fmaxf(acc[mi][ni][2] + q0, 0.f) * v0;
            pr[mi][1] += fmaxf(acc[mi][ni][3] + q1, 0.f) * v1;
        }
    }

    __syncthreads();
    #pragma unroll
    for (int mi = 0; mi < 2; mi++)
        #pragma unroll
        for (int j = 0; j < 2; j++) {
            float p = pr[mi][j];
            p += __shfl_xor_sync(0xFFFFFFFFu, p, 1);
            p += __shfl_xor_sync(0xFFFFFFFFu, p, 2);
            if (tig == 0) partial[wn * BM + wm * 32 + mi * 16 + j * 8 + gid] = p;
        }
    __syncthreads();

    if (tid < BM) {
        const float s = partial[0 * BM + tid] + partial[1 * BM + tid] +
                        partial[2 * BM + tid] + partial[3 * BM + tid];
        g_part[(size_t)nx * MTOT + m0 + tid] = s;
    }
}

// ---------------------------------------------------------------------------
// Sum 8 N-strip partials -> scores, softmax over T.
__global__ __launch_bounds__(256) void softmax_kernel(float* __restrict__ out)
{
    const int b = blockIdx.x;
    const int tid = threadIdx.x;
    __shared__ float red[256];

    float vals[8];
    float mx = -1e30f;
    #pragma unroll
    for (int j = 0; j < 8; j++) {
        const int t = tid + j * 256;
        float s = 0.f;
        #pragma unroll
        for (int nxi = 0; nxi < NTILES; nxi++)
            s += g_part[(size_t)nxi * MTOT + (size_t)b * TDIM + t];
        vals[j] = s;
        mx = fmaxf(mx, s);
    }

    red[tid] = mx;
    __syncthreads();
    #pragma unroll
    for (int o = 128; o > 0; o >>= 1) {
        if (tid < o) red[tid] = fmaxf(red[tid], red[tid + o]);
        __syncthreads();
    }
    const float m = red[0];
    __syncthreads();

    float sum = 0.f;
    #pragma unroll
    for (int j = 0; j < 8; j++) {
        vals[j] = expf(vals[j] - m);
        sum += vals[j];
    }
    red[tid] = sum;
    __syncthreads();
    #pragma unroll
    for (int o = 128; o > 0; o >>= 1) {
        if (tid < o) red[tid] += red[tid + o];
        __syncthreads();
    }
    const float inv = 1.f / red[0];

    #pragma unroll
    for (int j = 0; j < 8; j++)
        out[(size_t)b * TDIM + tid + j * 256] = vals[j] * inv;
}

// ---------------------------------------------------------------------------
extern "C" void kernel_launch(void* const* d_in, const int* in_sizes, int n_in,
                              void* d_out, int out_size)
{
    const float* hidden = (const float*)d_in[0];
    const float* enc    = (const float*)d_in[1];
    const float* W      = (const float*)d_in[2];
    const float* bias   = (const float*)d_in[3];
    const float* v      = (const float*)d_in[4];
    float* out = (float*)d_out;

    cudaFuncSetAttribute(bf_gemm, cudaFuncAttributeMaxDynamicSharedMemorySize, SMEM_TOTAL);

    conv_enc<<<65536, 256>>>((const float4*)enc);
    conv_w2<<<DDIM, 256>>>(W);
    qh_kernel<<<dim3(DDIM / 8, BDIM), 256>>>(hidden, W, bias);
    bf_gemm<<<dim3(NTILES, MTOT / BM), 512, SMEM_TOTAL>>>(v);
    softmax_kernel<<<BDIM, 256>>>(out);
}